// round 13
// baseline (speedup 1.0000x reference)
#include <cuda_runtime.h>
#include <cstdint>

// Embedding gather: out[i, :] = table[indices[i], :]
// indices: int32[4194304], table: float32[1000000, 16], out: float32[4194304, 16]
//
// Final journal:
//   R4 BEST 77.9us: 2 threads/row, 256-bit nc table loads, streaming stores.
//   R6 L2 evict_last hints: no-op.          R7 per-thread MLP x4: regress.
//   R8 1 thread/row: regress (L1tex).       R9 vocab tiling: regress (sparse warps).
//   R10 warp idx dedup: neutral.            R11 cp.async.bulk store offload: regress.
//   R12 write-through stores: regress (+traffic).
// Invariant across all: 66-70% DRAM busy @ 5.25-5.5 TB/s. The wall is HBM
// row-buffer efficiency on ~133MB of random 64B table reads mixed with a
// 272MB stream — not request supply. R4's shape is the optimum; this is the
// cleaned version (no createpolicy overhead, 512-thread blocks).

struct __align__(32) f8 { float4 a, b; };

__device__ __forceinline__ f8 ldg_nc_f8(const f8* p) {
    f8 v;
    asm volatile(
        "ld.global.nc.v8.f32 {%0,%1,%2,%3,%4,%5,%6,%7}, [%8];"
        : "=f"(v.a.x), "=f"(v.a.y), "=f"(v.a.z), "=f"(v.a.w),
          "=f"(v.b.x), "=f"(v.b.y), "=f"(v.b.z), "=f"(v.b.w)
        : "l"(p));
    return v;
}

static constexpr int ROW_HALVES = 2;   // 16 floats = 2 x 32 B halves per row

__global__ void __launch_bounds__(512) gather_kernel(
    const int* __restrict__ indices,
    const f8* __restrict__ table8,     // table as 32 B chunks: 2 per row
    float4* __restrict__ out4,
    int total_chunks)
{
    int j = blockIdx.x * blockDim.x + threadIdx.x;   // 32 B chunk id
    if (j >= total_chunks) return;

    int row = j >> 1;          // output row
    int sub = j & 1;           // which 32 B half of the row

    long long idx = (long long)__ldcs(&indices[row]);
    f8 v = ldg_nc_f8(&table8[idx * ROW_HALVES + sub]);

    // streaming stores: evict-first, coalesced 2 KB per warp
    __stcs(&out4[j * 2 + 0], v.a);
    __stcs(&out4[j * 2 + 1], v.b);
}

extern "C" void kernel_launch(void* const* d_in, const int* in_sizes, int n_in,
                              void* d_out, int out_size)
{
    // Resolve input order by size: indices = 4,194,304 elems, table = 16,000,000.
    int idx_slot = 0, tab_slot = 1;
    if (n_in >= 2 && in_sizes[0] > in_sizes[1]) { idx_slot = 1; tab_slot = 0; }

    const int* indices = (const int*)d_in[idx_slot];
    const f8*  table8  = (const f8*)d_in[tab_slot];
    float4*    out4    = (float4*)d_out;

    int num_indices  = in_sizes[idx_slot];           // 4,194,304
    int total_chunks = num_indices * ROW_HALVES;     // 8,388,608

    int threads = 512;
    int blocks  = (total_chunks + threads - 1) / threads;   // 16384
    gather_kernel<<<blocks, threads>>>(indices, table8, out4, total_chunks);
}

// round 14
// speedup vs baseline: 1.0483x; 1.0483x over previous
#include <cuda_runtime.h>
#include <cstdint>

// Embedding gather: out[i, :] = table[indices[i], :]
// indices: int32[4194304], table: float32[1000000, 16], out: float32[4194304, 16]
//
// FINAL — byte-exact reproduction of the best measured kernel (R4, 77.86us).
//
// Optimization journal (all measured on GB300/sm_103a):
//   R4  BEST 77.9us: 2 threads/row, 256-bit nc+cache_hint table loads,
//       __ldcs idx, __stcs stores, 256-thr blocks (405MB @ 5.25TB/s, DRAM 66%).
//   R6  L2 evict_last prefetch sweep: no-op on residency -> regress (+6us).
//   R7  per-thread MLP x4 batching: regress (L1tex queue contention).
//   R8  1 thread/row: regress (no warp line-sharing, L1 wavefront bound).
//   R9  vocab-range tiling: traffic 405->306MB but half-empty warps +
//       partial-line store RMW -> regress.
//   R10 warp-shuffle idx dedup: neutral.
//   R11 cp.async.bulk store offload (TMA path): regress.
//   R12 write-through stores: regress (+traffic).
//   R13 512-thr blocks: regress (occupancy 80->75%).
// Invariant: 66-70% DRAM busy @ 5.25-5.5TB/s across every request-path shape.
// Wall = HBM row-buffer efficiency on ~133MB random 64B reads mixed with a
// 272MB stream; not addressable from the kernel within harness rules.

struct __align__(32) f8 { float4 a, b; };

__device__ __forceinline__ f8 ldg_table_evict_last(const f8* p, uint64_t policy) {
    f8 v;
    asm volatile(
        "ld.global.nc.L2::cache_hint.v8.f32 {%0,%1,%2,%3,%4,%5,%6,%7}, [%8], %9;"
        : "=f"(v.a.x), "=f"(v.a.y), "=f"(v.a.z), "=f"(v.a.w),
          "=f"(v.b.x), "=f"(v.b.y), "=f"(v.b.z), "=f"(v.b.w)
        : "l"(p), "l"(policy));
    return v;
}

static constexpr int ROW_HALVES = 2;   // 16 floats = 2 x 32 B halves per row

__global__ void __launch_bounds__(256) gather_kernel(
    const int* __restrict__ indices,
    const f8* __restrict__ table8,     // table as 32 B chunks: 2 per row
    float4* __restrict__ out4,
    int num_indices)
{
    uint64_t policy;
    asm volatile("createpolicy.fractional.L2::evict_last.b64 %0, 1.0;" : "=l"(policy));

    int j = blockIdx.x * blockDim.x + threadIdx.x;   // 32 B chunk id
    int total = num_indices * ROW_HALVES;
    if (j >= total) return;

    int row = j >> 1;          // output row
    int sub = j & 1;           // which 32 B half of the row

    long long idx = (long long)__ldcs(&indices[row]);
    f8 v = ldg_table_evict_last(&table8[idx * ROW_HALVES + sub], policy);

    // streaming stores: evict-first, coalesced 2 KB per warp
    __stcs(&out4[j * 2 + 0], v.a);
    __stcs(&out4[j * 2 + 1], v.b);
}

extern "C" void kernel_launch(void* const* d_in, const int* in_sizes, int n_in,
                              void* d_out, int out_size)
{
    // Resolve input order by size: indices = 4,194,304 elems, table = 16,000,000.
    int idx_slot = 0, tab_slot = 1;
    if (n_in >= 2 && in_sizes[0] > in_sizes[1]) { idx_slot = 1; tab_slot = 0; }

    const int* indices = (const int*)d_in[idx_slot];
    const f8*  table8  = (const f8*)d_in[tab_slot];
    float4*    out4    = (float4*)d_out;

    int num_indices  = in_sizes[idx_slot];           // 4,194,304
    int total_chunks = num_indices * ROW_HALVES;     // 8,388,608

    int threads = 256;
    int blocks  = (total_chunks + threads - 1) / threads;   // 32768
    gather_kernel<<<blocks, threads>>>(indices, table8, out4, num_indices);
}